// round 12
// baseline (speedup 1.0000x reference)
#include <cuda_runtime.h>
#include <math.h>

// Problem constants
#define VD    256          // embedding dim D
#define VD4   64           // D / 4
#define LL    32           // tokens per sequence
#define MM    4096         // mems rows
#define CC    4096         // cands rows
#define ROWS  (MM + 1)     // mems_enc rows (mems + xs)
#define NSEQ  (MM + 2 + CC)// all sequences: mems, xs, ys, cands
#define EPS   1e-8f
#define NLHS  256          // blocks for att @ mems_enc partial stage

// Scratch (allocation-free: __device__ globals)
__device__ float g_mems_enc[ROWS * VD];
__device__ float g_cos[ROWS];
__device__ float g_partial[NLHS * VD];
__device__ float g_lhs[VD];
__device__ unsigned g_done = 0;     // last-block-done counter (reset by last block)

// ---------------------------------------------------------------------------
// Kernel 1: encode ALL sequences (mems, xs, ys, cands) — one launch.
// ceil(NSEQ/4) blocks x 256 threads; each 64-thread group = 1 sequence,
// thread j (0..63) owns one float4 column. ALL result stores streaming
// (__stcs): protect lt's L2 residency (measured best in R8).
// ---------------------------------------------------------------------------
__global__ void encode_kernel(const int* __restrict__ xs,
                              const int* __restrict__ mems,
                              const int* __restrict__ ys,
                              const int* __restrict__ cands,
                              const float* __restrict__ lt,
                              const float* __restrict__ freqs,
                              float* __restrict__ out_ys)
{
    __shared__ int   toks[4][LL];
    __shared__ float ws[4][LL];

    const int t = threadIdx.x;
    const int g = t >> 6;
    const int j = t & 63;
    const int s = blockIdx.x * 4 + g;

    const bool active = (s < NSEQ);

    const int* src = mems;
    float4* dst = nullptr;
    if (active) {
        if (s < MM) {
            src = mems + (size_t)s * LL;
            dst = reinterpret_cast<float4*>(g_mems_enc) + (size_t)s * VD4;
        } else if (s == MM) {
            src = xs;
            dst = reinterpret_cast<float4*>(g_mems_enc) + (size_t)MM * VD4;
        } else if (s == MM + 1) {
            src = ys;
            dst = reinterpret_cast<float4*>(out_ys);
        } else {
            const int c = s - (MM + 2);
            src = cands + (size_t)c * LL;
            dst = reinterpret_cast<float4*>(out_ys) + (size_t)(1 + c) * VD4;
        }
    }

    if (active && j < LL) {
        int tok = src[j];
        toks[g][j] = tok;
        float w = freqs[tok];
        float sq = w * w;
        #pragma unroll
        for (int o = 16; o; o >>= 1) sq += __shfl_xor_sync(0xFFFFFFFFu, sq, o);
        ws[g][j] = w * rsqrtf(sq);
    }
    __syncthreads();

    if (active) {
        const float4* __restrict__ lt4 = reinterpret_cast<const float4*>(lt);
        float4 acc = make_float4(0.f, 0.f, 0.f, 0.f);
        #pragma unroll
        for (int l = 0; l < LL; l++) {
            const float w = ws[g][l];
            const float4 e = lt4[(size_t)toks[g][l] * VD4 + j];
            acc.x = fmaf(w, e.x, acc.x);
            acc.y = fmaf(w, e.y, acc.y);
            acc.z = fmaf(w, e.z, acc.z);
            acc.w = fmaf(w, e.w, acc.w);
        }
        __stcs(dst + j, acc);
    }
}

// ---------------------------------------------------------------------------
// Kernel 2: cosine of every mems_enc row vs row M (xs). 4 rows per block,
// 64 threads per row, float4. (R8-identical.)
// ---------------------------------------------------------------------------
__global__ void cos_kernel()
{
    __shared__ float red[4][2][3];

    const int t = threadIdx.x;
    const int g = t >> 6;
    const int j = t & 63;
    const int r = blockIdx.x * 4 + g;
    if (r >= ROWS) return;

    const float4* __restrict__ enc4 = reinterpret_cast<const float4*>(g_mems_enc);
    const float4 mv = __ldcs(enc4 + (size_t)r * VD4 + j);
    const float4 xv = enc4[(size_t)MM * VD4 + j];

    float dot = mv.x * xv.x + mv.y * xv.y + mv.z * xv.z + mv.w * xv.w;
    float mn  = mv.x * mv.x + mv.y * mv.y + mv.z * mv.z + mv.w * mv.w;
    float xn  = xv.x * xv.x + xv.y * xv.y + xv.z * xv.z + xv.w * xv.w;

    #pragma unroll
    for (int o = 16; o; o >>= 1) {
        dot += __shfl_xor_sync(0xFFFFFFFFu, dot, o);
        mn  += __shfl_xor_sync(0xFFFFFFFFu, mn, o);
        xn  += __shfl_xor_sync(0xFFFFFFFFu, xn, o);
    }
    const int wig = j >> 5;
    if ((j & 31) == 0) {
        red[g][wig][0] = dot; red[g][wig][1] = mn; red[g][wig][2] = xn;
    }
    __syncthreads();

    if (j == 0) {
        float d  = red[g][0][0] + red[g][1][0];
        float m2 = red[g][0][1] + red[g][1][1];
        float x2 = red[g][0][2] + red[g][1][2];
        float an = fmaxf(sqrtf(x2), EPS);
        float bn = fmaxf(sqrtf(m2), EPS);
        g_cos[r] = d / (an * bn);
    }
}

// ---------------------------------------------------------------------------
// Kernel 3: fused softmax + partial att @ mems_enc + last-block final reduce.
// 256 blocks x 256 threads. enc reads via __ldcs (R8 policy); partial rows
// plain-stored (re-read by last block, L2-hot).
// ---------------------------------------------------------------------------
__global__ void lhs_kernel()
{
    __shared__ float  sred[8];
    __shared__ float4 scomb[4][VD4];
    __shared__ bool   s_last;

    const int t = threadIdx.x;
    const int lane = t & 31;
    const int wid  = t >> 5;

    // --- softmax stats over g_cos (L2-hot 16KB, redundant per block) ---
    float m = -INFINITY;
    for (int r = t; r < ROWS; r += 256) m = fmaxf(m, g_cos[r]);
    #pragma unroll
    for (int o = 16; o; o >>= 1) m = fmaxf(m, __shfl_xor_sync(0xFFFFFFFFu, m, o));
    if (lane == 0) sred[wid] = m;
    __syncthreads();
    {
        float mm = (t < 8) ? sred[t] : -INFINITY;
        if (wid == 0) {
            #pragma unroll
            for (int o = 4; o; o >>= 1) mm = fmaxf(mm, __shfl_xor_sync(0xFFFFFFFFu, mm, o));
            if (lane == 0) sred[0] = mm;
        }
    }
    __syncthreads();
    m = sred[0];
    __syncthreads();

    float s = 0.0f;
    for (int r = t; r < ROWS; r += 256) s += __expf(g_cos[r] - m);
    #pragma unroll
    for (int o = 16; o; o >>= 1) s += __shfl_xor_sync(0xFFFFFFFFu, s, o);
    if (lane == 0) sred[wid] = s;
    __syncthreads();
    {
        float ss = (t < 8) ? sred[t] : 0.0f;
        if (wid == 0) {
            #pragma unroll
            for (int o = 4; o; o >>= 1) ss += __shfl_xor_sync(0xFFFFFFFFu, ss, o);
            if (lane == 0) sred[0] = ss;
        }
    }
    __syncthreads();
    const float inv = 1.0f / sred[0];

    // --- partial weighted sum: 16 contiguous rows per block (4 per group) ---
    const int g = t >> 6;
    const int j = t & 63;
    const int base = (blockIdx.x * 4 + g) * 4;

    const float4* __restrict__ enc4 = reinterpret_cast<const float4*>(g_mems_enc);
    float4 acc = make_float4(0.f, 0.f, 0.f, 0.f);

    #pragma unroll
    for (int k = 0; k < 4; k++) {
        const int r = base + k;
        const float a = __expf(g_cos[r] - m) * inv;
        const float4 e = __ldcs(enc4 + (size_t)r * VD4 + j);
        acc.x = fmaf(a, e.x, acc.x);
        acc.y = fmaf(a, e.y, acc.y);
        acc.z = fmaf(a, e.z, acc.z);
        acc.w = fmaf(a, e.w, acc.w);
    }
    if (blockIdx.x == 0 && g == 0) {          // fold row 4096 (xs)
        const float a = __expf(g_cos[MM] - m) * inv;
        const float4 e = enc4[(size_t)MM * VD4 + j];
        acc.x = fmaf(a, e.x, acc.x);
        acc.y = fmaf(a, e.y, acc.y);
        acc.z = fmaf(a, e.z, acc.z);
        acc.w = fmaf(a, e.w, acc.w);
    }

    scomb[g][j] = acc;
    __syncthreads();

    if (g == 0) {
        float4 a0 = scomb[0][j], a1 = scomb[1][j], a2 = scomb[2][j], a3 = scomb[3][j];
        float4 r;
        r.x = (a0.x + a1.x) + (a2.x + a3.x);
        r.y = (a0.y + a1.y) + (a2.y + a3.y);
        r.z = (a0.z + a1.z) + (a2.z + a3.z);
        r.w = (a0.w + a1.w) + (a2.w + a3.w);
        reinterpret_cast<float4*>(g_partial)[(size_t)blockIdx.x * VD4 + j] = r;  // plain: keep L2
    }
    __syncthreads();

    // --- last-block-done: final reduce of 256 partial rows (L2-hot) ---
    if (t == 0) {
        __threadfence();
        unsigned old = atomicAdd(&g_done, 1u);
        s_last = (old == NLHS - 1);
    }
    __syncthreads();
    if (!s_last) return;
    if (t == 0) { g_done = 0; __threadfence(); }   // reset for next graph replay

    const float4* __restrict__ p4 = reinterpret_cast<const float4*>(g_partial);
    float4 fin = make_float4(0.f, 0.f, 0.f, 0.f);
    #pragma unroll 8
    for (int b = g * 64; b < (g + 1) * 64; b++) {
        const float4 v = p4[(size_t)b * VD4 + j];
        fin.x += v.x; fin.y += v.y; fin.z += v.z; fin.w += v.w;
    }
    scomb[g][j] = fin;
    __syncthreads();

    if (g == 0) {
        float4 a0 = scomb[0][j], a1 = scomb[1][j], a2 = scomb[2][j], a3 = scomb[3][j];
        float4 r;
        r.x = (a0.x + a1.x) + (a2.x + a3.x);
        r.y = (a0.y + a1.y) + (a2.y + a3.y);
        r.z = (a0.z + a1.z) + (a2.z + a3.z);
        r.w = (a0.w + a1.w) + (a2.w + a3.w);
        reinterpret_cast<float4*>(g_lhs)[j] = r;
    }
}

// ---------------------------------------------------------------------------
// Kernel 4: tile g_lhs into xs_out. 16 rows per block (4 per 64-thread group,
// 4 STG.128 per thread), 257 blocks — removes block-dispatch bottleneck.
// ---------------------------------------------------------------------------
__global__ void tile_kernel(float* __restrict__ out_xs)
{
    const int t = threadIdx.x;
    const int g = t >> 6;
    const int j = t & 63;
    const int base = blockIdx.x * 16 + g * 4;

    const float4 v = reinterpret_cast<const float4*>(g_lhs)[j];
    float4* out4 = reinterpret_cast<float4*>(out_xs);

    #pragma unroll
    for (int k = 0; k < 4; k++) {
        const int row = base + k;
        if (row <= CC)
            __stcs(out4 + (size_t)row * VD4 + j, v);
    }
}

// ---------------------------------------------------------------------------
extern "C" void kernel_launch(void* const* d_in, const int* in_sizes, int n_in,
                              void* d_out, int out_size)
{
    const int*   xs    = (const int*)  d_in[0];
    const int*   mems  = (const int*)  d_in[1];
    const int*   ys    = (const int*)  d_in[2];
    const int*   cands = (const int*)  d_in[3];
    const float* lt    = (const float*)d_in[4];
    const float* freqs = (const float*)d_in[5];

    float* out    = (float*)d_out;
    float* out_xs = out;                          // [C+1, D]
    float* out_ys = out + (size_t)(CC + 1) * VD;  // [C+1, D]

    encode_kernel<<<(NSEQ + 3) / 4, VD>>>(xs, mems, ys, cands, lt, freqs, out_ys);
    cos_kernel<<<(ROWS + 3) / 4, VD>>>();
    lhs_kernel<<<NLHS, VD>>>();
    tile_kernel<<<(CC + 16) / 16, VD>>>(out_xs);
}